// round 5
// baseline (speedup 1.0000x reference)
#include <cuda_runtime.h>
#include <math.h>
#include <stdint.h>

#define B_SZ 4
#define SEQ  2048
#define DIM  1024
#define NH   16
#define HD   64
#define D3   3072
#define M_TOT (B_SZ * SEQ)

// Scratch (device globals — no runtime allocation allowed)
__device__ float g_qkv[(size_t)M_TOT * D3];      // Q,K d-permuted; V part unused
__device__ float g_att[(size_t)M_TOT * DIM];     // attention out, d-permuted
__device__ float g_x  [(size_t)M_TOT * DIM];     // x, k-permuted, tf32
__device__ float g_w1 [(size_t)DIM * D3];        // w_qkv^T [3072][1024perm], tf32
__device__ float g_w2 [(size_t)DIM * DIM];       // w_out^T [1024][1024perm], tf32
__device__ float g_vT [(size_t)B_SZ * NH * HD * SEQ];  // V^T [b,h,d,key-perm]

// ---------------------------------------------------------------------------
// Helpers
// ---------------------------------------------------------------------------
__device__ __forceinline__ uint32_t f2tf32(float f) {
    uint32_t r;
    asm("cvt.rna.tf32.f32 %0, %1;" : "=r"(r) : "f"(f));
    return r;
}
__device__ __forceinline__ float tf32f(float f) {
    return __uint_as_float(f2tf32(f));
}
__device__ __forceinline__ void mma_tf32(float c[4], const uint32_t a[4], const uint32_t b[2]) {
    asm volatile(
        "mma.sync.aligned.m16n8k8.row.col.f32.tf32.tf32.f32 "
        "{%0,%1,%2,%3}, {%4,%5,%6,%7}, {%8,%9}, {%0,%1,%2,%3};"
        : "+f"(c[0]), "+f"(c[1]), "+f"(c[2]), "+f"(c[3])
        : "r"(a[0]), "r"(a[1]), "r"(a[2]), "r"(a[3]), "r"(b[0]), "r"(b[1]));
}
__device__ __forceinline__ void cpasync16(void* smem, const void* gmem) {
    uint32_t sa = (uint32_t)__cvta_generic_to_shared(smem);
    asm volatile("cp.async.cg.shared.global [%0], [%1], 16;" :: "r"(sa), "l"(gmem));
}
#define CP_COMMIT() asm volatile("cp.async.commit_group;" ::: "memory")
#define CP_WAIT(N)  asm volatile("cp.async.wait_group %0;" :: "n"(N) : "memory")
#define U(x) __float_as_uint(x)

// ---------------------------------------------------------------------------
// Pre-kernels: tf32-round + k-permutation (p(k) = (k%4)*8 + k/4 per 32-block)
// ---------------------------------------------------------------------------
__global__ __launch_bounds__(256) void round_perm(
    const float* __restrict__ in, float* __restrict__ out, int n4, int Kd)
{
    int i = blockIdx.x * blockDim.x + threadIdx.x;
    int stride = gridDim.x * blockDim.x;
    int K4 = Kd / 4;
    for (; i < n4; i += stride) {
        int row = i / K4;
        int col = (i - row * K4) * 4;
        float4 v = ((const float4*)in)[i];
        float* o = out + (size_t)row * Kd + (col & ~31) + ((col & 31) >> 2);
        o[0]  = tf32f(v.x);
        o[8]  = tf32f(v.y);
        o[16] = tf32f(v.z);
        o[24] = tf32f(v.w);
    }
}

// in [K][N] row-major -> out [N][K] with k permuted per 32-block, tf32-rounded.
__global__ __launch_bounds__(256) void transpose_round_perm(
    const float* __restrict__ in, float* __restrict__ out, int K, int N)
{
    __shared__ float t[32][33];
    const int k0 = blockIdx.y * 32, n0 = blockIdx.x * 32;
    const int tx = threadIdx.x, ty = threadIdx.y;
#pragma unroll
    for (int j = 0; j < 4; ++j)
        t[ty + j * 8][tx] = in[(size_t)(k0 + ty + j * 8) * N + n0 + tx];
    __syncthreads();
    const int ptx = (tx & 3) * 8 + (tx >> 2);
#pragma unroll
    for (int j = 0; j < 4; ++j) {
        int row = ty + j * 8;
        out[(size_t)(n0 + row) * K + k0 + ptx] = tf32f(t[tx][row]);
    }
}

// ---------------------------------------------------------------------------
// tf32 TC GEMM: C = A@W + bias. A [M][Kperm], Wt [N][Kperm] (both tf32).
// BM=BN=128, BK=32, 256 thr, warp tile 64x32, vectorized LDS.128 fragments.
// MODE 0: plain fp32 epilogue. MODE 1: QKV epilogue (Q/K perm to C=g_qkv,
// V transposed+key-perm to Cv=g_vT), tf32-rounded.
// ---------------------------------------------------------------------------
#define TP 36                       // tile pitch (32 + 4; 36%32=4 -> conflict-free)
#define TILE_WORDS (128 * TP)

template<int MODE>
__global__ __launch_bounds__(256, 2) void gemm_tc(
    const float* __restrict__ A, const float* __restrict__ Wt,
    const float* __restrict__ bias, float* __restrict__ C,
    float* __restrict__ Cv, int M, int N, int K)
{
    extern __shared__ float sm[];
    float* AsB = sm;                       // [2][128*36]
    float* BsB = sm + 2 * TILE_WORDS;      // [2][128*36]

    const int tid  = threadIdx.x;
    const int lane = tid & 31;
    const int warp = tid >> 5;
    const int warpM = warp >> 2;
    const int warpN = warp & 3;
    const int g  = lane >> 2;
    const int t4 = lane & 3;
    const int mBase = blockIdx.y * 128;
    const int nBase = blockIdx.x * 128;

    int row_[4], c4_[4];
#pragma unroll
    for (int f = 0; f < 4; ++f) {
        int idx = tid + f * 256;
        row_[f] = idx >> 3;  c4_[f] = (idx & 7) * 4;
    }

    float acc[4][4][4];
#pragma unroll
    for (int mi = 0; mi < 4; ++mi)
#pragma unroll
        for (int ni = 0; ni < 4; ++ni)
#pragma unroll
            for (int r = 0; r < 4; ++r) acc[mi][ni][r] = 0.0f;

    // prologue
    {
        float* As = AsB; float* Bs = BsB;
#pragma unroll
        for (int f = 0; f < 4; ++f) {
            cpasync16(&As[row_[f] * TP + c4_[f]], &A [(size_t)(mBase + row_[f]) * K + c4_[f]]);
            cpasync16(&Bs[row_[f] * TP + c4_[f]], &Wt[(size_t)(nBase + row_[f]) * K + c4_[f]]);
        }
        CP_COMMIT();
    }

    int stage = 0;
    for (int k0 = 0; k0 < K; k0 += 32) {
        const bool hasNext = (k0 + 32) < K;
        if (hasNext) {
            float* As = AsB + (stage ^ 1) * TILE_WORDS;
            float* Bs = BsB + (stage ^ 1) * TILE_WORDS;
#pragma unroll
            for (int f = 0; f < 4; ++f) {
                cpasync16(&As[row_[f] * TP + c4_[f]],
                          &A [(size_t)(mBase + row_[f]) * K + k0 + 32 + c4_[f]]);
                cpasync16(&Bs[row_[f] * TP + c4_[f]],
                          &Wt[(size_t)(nBase + row_[f]) * K + k0 + 32 + c4_[f]]);
            }
            CP_COMMIT();
            CP_WAIT(1);
        } else {
            CP_WAIT(0);
        }
        __syncthreads();

        const float* As = AsB + stage * TILE_WORDS;
        const float* Bs = BsB + stage * TILE_WORDS;
#pragma unroll
        for (int jp = 0; jp < 2; ++jp) {
            const int off = t4 * 8 + jp * 4;
            float4 bv[4];
#pragma unroll
            for (int ni = 0; ni < 4; ++ni)
                bv[ni] = *(const float4*)&Bs[(warpN * 32 + ni * 8 + g) * TP + off];
#pragma unroll
            for (int mi = 0; mi < 4; ++mi) {
                float4 av = *(const float4*)&As[(warpM * 64 + mi * 16 + g    ) * TP + off];
                float4 aw = *(const float4*)&As[(warpM * 64 + mi * 16 + g + 8) * TP + off];
                uint32_t a0[4] = {U(av.x), U(aw.x), U(av.y), U(aw.y)};
                uint32_t a1[4] = {U(av.z), U(aw.z), U(av.w), U(aw.w)};
#pragma unroll
                for (int ni = 0; ni < 4; ++ni) {
                    uint32_t b0[2] = {U(bv[ni].x), U(bv[ni].y)};
                    mma_tf32(acc[mi][ni], a0, b0);
                    uint32_t b1[2] = {U(bv[ni].z), U(bv[ni].w)};
                    mma_tf32(acc[mi][ni], a1, b1);
                }
            }
        }
        __syncthreads();
        stage ^= 1;
    }

    // Epilogue
    if (MODE == 0) {
#pragma unroll
        for (int mi = 0; mi < 4; ++mi) {
            int row0 = mBase + warpM * 64 + mi * 16 + g;
#pragma unroll
            for (int ni = 0; ni < 4; ++ni) {
                int c0 = nBase + warpN * 32 + ni * 8 + t4 * 2;
                float2 bv2 = *(const float2*)&bias[c0];
                float2 o0, o1;
                o0.x = acc[mi][ni][0] + bv2.x;
                o0.y = acc[mi][ni][1] + bv2.y;
                o1.x = acc[mi][ni][2] + bv2.x;
                o1.y = acc[mi][ni][3] + bv2.y;
                *(float2*)&C[(size_t)row0 * N + c0]       = o0;
                *(float2*)&C[(size_t)(row0 + 8) * N + c0] = o1;
            }
        }
    } else {
        const int region = nBase >> 10;   // 0=Q, 1=K, 2=V (uniform per CTA)
#pragma unroll
        for (int mi = 0; mi < 4; ++mi) {
            int row0 = mBase + warpM * 64 + mi * 16 + g;
#pragma unroll
            for (int ni = 0; ni < 4; ++ni) {
                int c0 = nBase + warpN * 32 + ni * 8 + t4 * 2;
                float v00 = tf32f(acc[mi][ni][0] + bias[c0]);
                float v01 = tf32f(acc[mi][ni][1] + bias[c0 + 1]);
                float v10 = tf32f(acc[mi][ni][2] + bias[c0]);
                float v11 = tf32f(acc[mi][ni][3] + bias[c0 + 1]);
                if (region < 2) {
                    int pbase = (c0 & ~31) + 16 * (t4 & 1) + 2 * (ni & 3) + (t4 >> 1);
                    C[(size_t)row0 * N + pbase]           = v00;
                    C[(size_t)row0 * N + pbase + 8]       = v01;
                    C[(size_t)(row0 + 8) * N + pbase]     = v10;
                    C[(size_t)(row0 + 8) * N + pbase + 8] = v11;
                } else {
                    // V -> vT [b,h,d,key-perm]
                    float vals[4] = {v00, v01, v10, v11};
#pragma unroll
                    for (int e = 0; e < 4; ++e) {
                        int r = row0 + (e >> 1) * 8;
                        int c = c0 + (e & 1);
                        int bb = r >> 11;
                        int key = r & 2047;
                        int hd_ = c - 2048;
                        int hh = hd_ >> 6;
                        int dd = hd_ & 63;
                        int kp = (key & ~31) + (key & 3) * 8 + ((key & 31) >> 2);
                        Cv[(((size_t)bb * NH + hh) * HD + dd) * SEQ + kp] = vals[e];
                    }
                }
            }
        }
    }
}

// ---------------------------------------------------------------------------
// Causal flash attention, tf32 TC, fully vectorized fragment loads.
// Q frags hoisted to registers; P aliases Q smem. V read from vT.
// ---------------------------------------------------------------------------
#define AQP 68
#define OFF_K (128 * AQP)
#define OFF_V (OFF_K + 2 * 64 * AQP)
#define ATT_SMEM ((OFF_V + 2 * 64 * AQP) * 4)

__global__ __launch_bounds__(256, 2) void attn_fwd_tc(
    const float* __restrict__ qkv, const float* __restrict__ vT,
    float* __restrict__ att)
{
    extern __shared__ float sm[];
    float* QP = sm;   // Q tile, later reused as P tile (warp-private rows)

    const int qt = blockIdx.x;
    const int h  = blockIdx.y;
    const int b  = blockIdx.z;
    const int qBase = qt * 128;
    const int tid  = threadIdx.x;
    const int lane = tid & 31;
    const int warp = tid >> 5;
    const int g  = lane >> 2;
    const int t4 = lane & 3;
    const int wrow = warp * 16;

    const float* kvK = qkv + (size_t)(b * SEQ) * D3 + DIM + h * HD;
    const float* vtb = vT + (((size_t)b * NH + h) * HD) * SEQ;

    // prefetch K/V tile 0
    {
        float* Ks = sm + OFF_K;
        float* Vs = sm + OFF_V;
#pragma unroll
        for (int it = 0; it < 4; ++it) {
            int i = tid + it * 256;
            int r = i >> 4, c4 = (i & 15) * 4;
            cpasync16(&Ks[r * AQP + c4], kvK + (size_t)r * D3 + c4);
            cpasync16(&Vs[r * AQP + c4], vtb + (size_t)r * SEQ + c4);
        }
        CP_COMMIT();
    }

    // Load + scale Q tile (128x64, d-permuted in gmem; raw copy preserves perm)
    const float* qb = qkv + (size_t)(b * SEQ + qBase) * D3 + h * HD;
#pragma unroll
    for (int it = 0; it < 8; ++it) {
        int i = tid + it * 256;
        int r = i >> 4, c4 = (i & 15) * 4;
        float4 v = *(const float4*)(qb + (size_t)r * D3 + c4);
        float4 s;
        s.x = v.x * 0.125f; s.y = v.y * 0.125f; s.z = v.z * 0.125f; s.w = v.w * 0.125f;
        *(float4*)&QP[r * AQP + c4] = s;
    }
    __syncthreads();

    // Hoist Q fragments (warp-private rows); QP becomes P afterwards.
    float4 qv[4], qw[4];
#pragma unroll
    for (int idx = 0; idx < 4; ++idx) {
        int off = (idx >> 1) * 32 + t4 * 8 + (idx & 1) * 4;
        qv[idx] = *(const float4*)&QP[(wrow + g    ) * AQP + off];
        qw[idx] = *(const float4*)&QP[(wrow + g + 8) * AQP + off];
    }

    float m_i[2] = {-INFINITY, -INFINITY};
    float l_i[2] = {0.0f, 0.0f};
    float O[8][4];
#pragma unroll
    for (int ni = 0; ni < 8; ++ni)
#pragma unroll
        for (int r = 0; r < 4; ++r) O[ni][r] = 0.0f;

    const int nkt = qBase / 64 + 2;
    for (int kt = 0; kt < nkt; ++kt) {
        const int stg = kt & 1;
        const bool hasNext = (kt + 1) < nkt;
        if (hasNext) {
            float* Kn = sm + OFF_K + (stg ^ 1) * 64 * AQP;
            float* Vn = sm + OFF_V + (stg ^ 1) * 64 * AQP;
            const float* srcK = kvK + (size_t)(kt + 1) * 64 * D3;
            const float* srcV = vtb + (kt + 1) * 64;
#pragma unroll
            for (int it = 0; it < 4; ++it) {
                int i = tid + it * 256;
                int r = i >> 4, c4 = (i & 15) * 4;
                cpasync16(&Kn[r * AQP + c4], srcK + (size_t)r * D3 + c4);
                cpasync16(&Vn[r * AQP + c4], srcV + (size_t)r * SEQ + c4);
            }
            CP_COMMIT();
            CP_WAIT(1);
        } else {
            CP_WAIT(0);
        }
        __syncthreads();

        const float* Ks = sm + OFF_K + stg * 64 * AQP;
        const float* Vs = sm + OFF_V + stg * 64 * AQP;
        const int ktBase = kt * 64;

        // S = Q K^T (vectorized LDS.128 fragments)
        float sc[8][4];
#pragma unroll
        for (int ni = 0; ni < 8; ++ni)
#pragma unroll
            for (int r = 0; r < 4; ++r) sc[ni][r] = 0.0f;

#pragma unroll
        for (int idx = 0; idx < 4; ++idx) {
            const int off = (idx >> 1) * 32 + t4 * 8 + (idx & 1) * 4;
            uint32_t a0[4] = {U(qv[idx].x), U(qw[idx].x), U(qv[idx].y), U(qw[idx].y)};
            uint32_t a1[4] = {U(qv[idx].z), U(qw[idx].z), U(qv[idx].w), U(qw[idx].w)};
#pragma unroll
            for (int ni = 0; ni < 8; ++ni) {
                float4 kv = *(const float4*)&Ks[(ni * 8 + g) * AQP + off];
                uint32_t b0[2] = {U(kv.x), U(kv.y)};
                mma_tf32(sc[ni], a0, b0);
                uint32_t b1[2] = {U(kv.z), U(kv.w)};
                mma_tf32(sc[ni], a1, b1);
            }
        }

        // Causal mask (logical columns; mma output layout is perm-independent)
        if (ktBase + 63 > qBase + wrow) {
            const int r0 = qBase + wrow + g;
            const int r1 = r0 + 8;
#pragma unroll
            for (int ni = 0; ni < 8; ++ni) {
                int c0 = ktBase + ni * 8 + t4 * 2;
                int c1 = c0 + 1;
                if (c0 > r0) sc[ni][0] = -1e30f;
                if (c1 > r0) sc[ni][1] = -1e30f;
                if (c0 > r1) sc[ni][2] = -1e30f;
                if (c1 > r1) sc[ni][3] = -1e30f;
            }
        }

        // Online softmax
#pragma unroll
        for (int hrow = 0; hrow < 2; ++hrow) {
            const int i0 = hrow * 2, i1 = hrow * 2 + 1;
            float tm = -INFINITY;
#pragma unroll
            for (int ni = 0; ni < 8; ++ni)
                tm = fmaxf(tm, fmaxf(sc[ni][i0], sc[ni][i1]));
            tm = fmaxf(tm, __shfl_xor_sync(0xffffffffu, tm, 1, 4));
            tm = fmaxf(tm, __shfl_xor_sync(0xffffffffu, tm, 2, 4));
            float m_new = fmaxf(m_i[hrow], tm);
            float alpha = __expf(m_i[hrow] - m_new);
            float rs = 0.0f;
#pragma unroll
            for (int ni = 0; ni < 8; ++ni) {
                sc[ni][i0] = __expf(sc[ni][i0] - m_new);
                sc[ni][i1] = __expf(sc[ni][i1] - m_new);
                rs += sc[ni][i0] + sc[ni][i1];
            }
            rs += __shfl_xor_sync(0xffffffffu, rs, 1, 4);
            rs += __shfl_xor_sync(0xffffffffu, rs, 2, 4);
            l_i[hrow] = l_i[hrow] * alpha + rs;
            m_i[hrow] = m_new;
#pragma unroll
            for (int ni = 0; ni < 8; ++ni) {
                O[ni][i0] *= alpha;
                O[ni][i1] *= alpha;
            }
        }

        // P -> smem (key-permuted, tf32), warp-private rows
#pragma unroll
        for (int ni = 0; ni < 8; ++ni) {
            int pbase = (ni & 4) * 8 + 16 * (t4 & 1) + 2 * (ni & 3) + (t4 >> 1);
            QP[(wrow + g    ) * AQP + pbase]     = tf32f(sc[ni][0]);
            QP[(wrow + g    ) * AQP + pbase + 8] = tf32f(sc[ni][1]);
            QP[(wrow + g + 8) * AQP + pbase]     = tf32f(sc[ni][2]);
            QP[(wrow + g + 8) * AQP + pbase + 8] = tf32f(sc[ni][3]);
        }
        __syncwarp();

        // O += P @ V (vectorized)
#pragma unroll
        for (int idx = 0; idx < 4; ++idx) {
            const int off = (idx >> 1) * 32 + t4 * 8 + (idx & 1) * 4;
            float4 pv = *(const float4*)&QP[(wrow + g    ) * AQP + off];
            float4 pw = *(const float4*)&QP[(wrow + g + 8) * AQP + off];
            uint32_t a0[4] = {U(pv.x), U(pw.x), U(pv.y), U(pw.y)};
            uint32_t a1[4] = {U(pv.z), U(pw.z), U(pv.w), U(pw.w)};
#pragma unroll
            for (int ni = 0; ni < 8; ++ni) {
                float4 vv = *(const float4*)&Vs[(ni * 8 + g) * AQP + off];
                uint32_t b0[2] = {U(vv.x), U(vv.y)};
                mma_tf32(O[ni], a0, b0);
                uint32_t b1[2] = {U(vv.z), U(vv.w)};
                mma_tf32(O[ni], a1, b1);
            }
        }
        __syncthreads();
    }

    // Epilogue: normalize, tf32-round, write d-permuted (feeds out-GEMM)
    float* ob = att + (size_t)(b * SEQ + qBase + wrow) * DIM + h * HD;
    const float inv0 = 1.0f / l_i[0];
    const float inv1 = 1.0f / l_i[1];
#pragma unroll
    for (int ni = 0; ni < 8; ++ni) {
        int pbase = (ni & 4) * 8 + 16 * (t4 & 1) + 2 * (ni & 3) + (t4 >> 1);
        ob[(size_t)g * DIM + pbase]           = tf32f(O[ni][0] * inv0);
        ob[(size_t)g * DIM + pbase + 8]       = tf32f(O[ni][1] * inv0);
        ob[(size_t)(g + 8) * DIM + pbase]     = tf32f(O[ni][2] * inv1);
        ob[(size_t)(g + 8) * DIM + pbase + 8] = tf32f(O[ni][3] * inv1);
    }
}

// ---------------------------------------------------------------------------
extern "C" void kernel_launch(void* const* d_in, const int* in_sizes, int n_in,
                              void* d_out, int out_size)
{
    const float* x     = (const float*)d_in[0];
    const float* w_qkv = (const float*)d_in[1];
    const float* b_qkv = (const float*)d_in[2];
    const float* w_out = (const float*)d_in[3];
    const float* b_out = (const float*)d_in[4];
    float* out = (float*)d_out;

    float *qkv_p, *att_p, *x_p, *w1_p, *w2_p, *vT_p;
    cudaGetSymbolAddress((void**)&qkv_p, g_qkv);
    cudaGetSymbolAddress((void**)&att_p, g_att);
    cudaGetSymbolAddress((void**)&x_p,   g_x);
    cudaGetSymbolAddress((void**)&w1_p,  g_w1);
    cudaGetSymbolAddress((void**)&w2_p,  g_w2);
    cudaGetSymbolAddress((void**)&vT_p,  g_vT);

    // 0) Pre-round + permute/transpose inputs
    round_perm<<<1024, 256>>>(x, x_p, (int)((size_t)M_TOT * DIM / 4), DIM);
    transpose_round_perm<<<dim3(D3 / 32, DIM / 32), dim3(32, 8)>>>(w_qkv, w1_p, DIM, D3);
    transpose_round_perm<<<dim3(DIM / 32, DIM / 32), dim3(32, 8)>>>(w_out, w2_p, DIM, DIM);

    const int gemm_smem = 4 * TILE_WORDS * (int)sizeof(float);  // 73728
    cudaFuncSetAttribute(gemm_tc<1>, cudaFuncAttributeMaxDynamicSharedMemorySize, gemm_smem);
    cudaFuncSetAttribute(gemm_tc<0>, cudaFuncAttributeMaxDynamicSharedMemorySize, gemm_smem);

    // 1) QKV projection (special epilogue: Q/K perm, V transposed)
    gemm_tc<1><<<dim3(D3 / 128, M_TOT / 128), 256, gemm_smem>>>(
        x_p, w1_p, b_qkv, qkv_p, vT_p, M_TOT, D3, DIM);

    // 2) Causal flash attention
    cudaFuncSetAttribute(attn_fwd_tc, cudaFuncAttributeMaxDynamicSharedMemorySize, ATT_SMEM);
    attn_fwd_tc<<<dim3(SEQ / 128, NH, B_SZ), 256, ATT_SMEM>>>(qkv_p, vT_p, att_p);

    // 3) Output projection (plain fp32 epilogue)
    gemm_tc<0><<<dim3(DIM / 128, M_TOT / 128), 256, gemm_smem>>>(
        att_p, w2_p, b_out, out, nullptr, M_TOT, DIM, DIM);
}